// round 3
// baseline (speedup 1.0000x reference)
#include <cuda_runtime.h>

#define NB      2
#define CC      512
#define SS      256
#define DCHUNK  32
#define NCHUNK  (CC / DCHUNK)     // 16
#define THREADS 512
#define WARPS   16

// smem (floats): ks/vs double-buffered only: 4*DCHUNK*SS = 32768 floats (131072 B)
#define KS_FLOATS   (2 * DCHUNK * SS)
#define SMEM_BYTES  (4 * DCHUNK * SS * 4)

typedef unsigned long long ull;

__device__ __forceinline__ ull add2(ull a, ull b) {
    ull c; asm("add.rn.f32x2 %0, %1, %2;" : "=l"(c) : "l"(a), "l"(b)); return c;
}
__device__ __forceinline__ ull mul2(ull a, ull b) {
    ull c; asm("mul.rn.f32x2 %0, %1, %2;" : "=l"(c) : "l"(a), "l"(b)); return c;
}
__device__ __forceinline__ ull fma2(ull a, ull b, ull c) {
    ull d; asm("fma.rn.f32x2 %0, %1, %2, %3;" : "=l"(d) : "l"(a), "l"(b), "l"(c)); return d;
}
__device__ __forceinline__ ull abs2(ull a) {
    return a & 0x7FFFFFFF7FFFFFFFULL;           // 2x LOP3 on the ALU pipe
}
__device__ __forceinline__ ull pack2(float x, float y) {
    ull r; asm("mov.b64 %0, {%1, %2};" : "=l"(r) : "f"(x), "f"(y)); return r;
}
__device__ __forceinline__ ull dup2(float x) { return pack2(x, x); }
__device__ __forceinline__ float hadd2(ull a) {
    float lo = __uint_as_float((unsigned)a);
    float hi = __uint_as_float((unsigned)(a >> 32));
    return lo + hi;
}
__device__ __forceinline__ void cp_async16(void* sdst, const void* gsrc) {
    unsigned a = (unsigned)__cvta_generic_to_shared(sdst);
    asm volatile("cp.async.cg.shared.global [%0], [%1], 16;\n" :: "r"(a), "l"(gsrc));
}

extern __shared__ __align__(16) float smem[];

__device__ __forceinline__ void stage_chunk(const float* kg, const float* vg,
                                            float* kd, float* vd, int tid) {
    const float4* kg4 = (const float4*)kg;
    const float4* vg4 = (const float4*)vg;
#pragma unroll
    for (int j = 0; j < 4; j++) {               // 2048 float4 per tensor / 512 thr
        int idx = tid + j * THREADS;
        cp_async16(kd + idx * 4, kg4 + idx);
        cp_async16(vd + idx * 4, vg4 + idx);
    }
    asm volatile("cp.async.commit_group;\n" ::: "memory");
}

__global__ void __launch_bounds__(THREADS, 1)
laplace_attn_kernel(const float* __restrict__ q,
                    const float* __restrict__ k,
                    const float* __restrict__ v,
                    float* __restrict__ out)
{
    float* ks = smem;                            // [2][DCHUNK][SS]
    float* vs = smem + KS_FLOATS;                // [2][DCHUNK][SS]

    const int tid = threadIdx.x;
    const int w   = tid >> 5;
    const int l   = tid & 31;
    const int g   = w & 1;                       // row-group (4 rows each)
    const int ds  = w >> 1;                      // d-split 0..7 (4 d's per 32-chunk)
    const int n   = blockIdx.x / (CC / 8);
    const int ct  = blockIdx.x % (CC / 8);
    const int c0  = ct * 8 + g * 4;              // first of this warp's 4 rows

    // Lane's s-slice: {4l..4l+3} and {128+4l..128+4l+3} (lane-contiguous
    // float4 blocks -> every smem LDS.128 is bank-conflict-free).
    ull nq[4][4];
#pragma unroll
    for (int r = 0; r < 4; r++) {
        const float* qp = q + ((size_t)n * CC + c0 + r) * SS;
        float4 a = *(const float4*)(qp + 4 * l);
        float4 b = *(const float4*)(qp + 128 + 4 * l);
        nq[r][0] = pack2(-a.x, -a.y);
        nq[r][1] = pack2(-a.z, -a.w);
        nq[r][2] = pack2(-b.x, -b.y);
        nq[r][3] = pack2(-b.z, -b.w);
    }

    const float* kbase = k + (size_t)n * CC * SS;
    const float* vbase = v + (size_t)n * CC * SS;

    ull acc[4][4];
#pragma unroll
    for (int r = 0; r < 4; r++)
#pragma unroll
        for (int j = 0; j < 4; j++) acc[r][j] = 0ULL;

    float m_own = -1e30f;                        // lane's row = (l&15)>>2
    float lsum_own = 0.f;

    stage_chunk(kbase, vbase, ks, vs, tid);      // chunk 0 -> buffer 0

#pragma unroll 1
    for (int ch = 0; ch < NCHUNK; ch++) {
        const int p = ch & 1;
        if (ch + 1 < NCHUNK) {
            stage_chunk(kbase + (size_t)(ch + 1) * DCHUNK * SS,
                        vbase + (size_t)(ch + 1) * DCHUNK * SS,
                        ks + (1 - p) * DCHUNK * SS,
                        vs + (1 - p) * DCHUNK * SS, tid);
            asm volatile("cp.async.wait_group 1;\n" ::: "memory");
        } else {
            asm volatile("cp.async.wait_group 0;\n" ::: "memory");
        }
        __syncthreads();

        const float* kc = ks + p * DCHUNK * SS;
        const float* vc = vs + p * DCHUNK * SS;

        // ---- distance partials: 4 d's x 4 rows, packed f32x2, in regs ----
        float vv[16];
#pragma unroll
        for (int dl = 0; dl < 4; dl++) {
            const int d = ds * 4 + dl;
            const ulonglong2 ka = *(const ulonglong2*)(kc + d * SS + 4 * l);
            const ulonglong2 kb = *(const ulonglong2*)(kc + d * SS + 128 + 4 * l);
#pragma unroll
            for (int r = 0; r < 4; r++) {
                ull t0 = abs2(add2(ka.x, nq[r][0]));
                ull t1 = abs2(add2(ka.y, nq[r][1]));
                ull t2 = abs2(add2(kb.x, nq[r][2]));
                ull t3 = abs2(add2(kb.y, nq[r][3]));
                vv[r * 4 + dl] = hadd2(add2(add2(t0, t1), add2(t2, t3)));
            }
        }

        // ---- register butterfly reduce: lane l ends with e = l&15,
        //      summed over its 16-lane half; strides 8,4,2,1 ----
#pragma unroll
        for (int j = 3; j >= 0; j--) {
            const int cnt = 1 << j;
            const bool hi = (l >> j) & 1;
#pragma unroll
            for (int i = 0; i < cnt; i++) {
                float keep = hi ? vv[i + cnt] : vv[i];
                float send = hi ? vv[i] : vv[i + cnt];
                vv[i] = keep + __shfl_xor_sync(0xffffffffu, send, 1 << j);
            }
        }
        float dist = vv[0] + __shfl_xor_sync(0xffffffffu, vv[0], 16);
        const float wv = -0.5f * dist;           // logits = -dist/SCALE, SCALE=2

        // ---- per-warp online softmax over this warp's 4-d segment ----
        float cm = wv;
        cm = fmaxf(cm, __shfl_xor_sync(0xffffffffu, cm, 1));
        cm = fmaxf(cm, __shfl_xor_sync(0xffffffffu, cm, 2));
        const float mnew = fmaxf(m_own, cm);
        const float corr = __expf(m_own - mnew);
        const float pv   = __expf(wv - mnew);
        float ps = pv + __shfl_xor_sync(0xffffffffu, pv, 1);
        ps += __shfl_xor_sync(0xffffffffu, ps, 2);
        lsum_own = lsum_own * corr + ps;
        m_own = mnew;
#pragma unroll
        for (int r = 0; r < 4; r++) {
            const float cr = __shfl_sync(0xffffffffu, corr, r * 4);
            const ull c2 = dup2(cr);
#pragma unroll
            for (int j = 0; j < 4; j++) acc[r][j] = mul2(acc[r][j], c2);
        }

        // ---- P @ V: packed FMA, p broadcast via shfl ----
#pragma unroll
        for (int dl = 0; dl < 4; dl++) {
            const int d = ds * 4 + dl;
            const ulonglong2 va = *(const ulonglong2*)(vc + d * SS + 4 * l);
            const ulonglong2 vb = *(const ulonglong2*)(vc + d * SS + 128 + 4 * l);
#pragma unroll
            for (int r = 0; r < 4; r++) {
                const float pj = __shfl_sync(0xffffffffu, pv, r * 4 + dl);
                const ull p2 = dup2(pj);
                acc[r][0] = fma2(p2, va.x, acc[r][0]);
                acc[r][1] = fma2(p2, va.y, acc[r][1]);
                acc[r][2] = fma2(p2, vb.x, acc[r][2]);
                acc[r][3] = fma2(p2, vb.y, acc[r][3]);
            }
        }
        __syncthreads();                         // buffer p reusable
    }

    // ================= epilogue: merge the 8 d-split segments =================
    float* accbuf = smem;                        // [8 rows][8 splits][256] (reuses ks)
    float* stats  = smem + 8 * 8 * 256;          // [8 rows][8 splits][2]  (reuses vs)

#pragma unroll
    for (int r = 0; r < 4; r++) {
        const int row = g * 4 + r;
        float* dst = accbuf + (row * 8 + ds) * 256;
        *(ulonglong2*)(dst + 4 * l)       = make_ulonglong2(acc[r][0], acc[r][1]);
        *(ulonglong2*)(dst + 128 + 4 * l) = make_ulonglong2(acc[r][2], acc[r][3]);
    }
    if (l < 16 && (l & 3) == 0) {
        const int row = g * 4 + (l >> 2);
        stats[(row * 8 + ds) * 2 + 0] = m_own;
        stats[(row * 8 + ds) * 2 + 1] = lsum_own;
    }
    __syncthreads();

    {
        const int row  = w >> 1;
        const int half = w & 1;
        const int sb   = half * 128 + l * 4;

        float M = -1e30f;
#pragma unroll
        for (int i = 0; i < 8; i++) M = fmaxf(M, stats[(row * 8 + i) * 2]);

        float L = 0.f;
        ull o0 = 0ULL, o1 = 0ULL;
#pragma unroll
        for (int i = 0; i < 8; i++) {
            const float sc = __expf(stats[(row * 8 + i) * 2] - M);
            L += stats[(row * 8 + i) * 2 + 1] * sc;
            const ulonglong2 a = *(const ulonglong2*)(accbuf + (row * 8 + i) * 256 + sb);
            const ull s2 = dup2(sc);
            o0 = fma2(s2, a.x, o0);
            o1 = fma2(s2, a.y, o1);
        }
        const ull i2 = dup2(1.f / L);
        o0 = mul2(o0, i2);
        o1 = mul2(o1, i2);

        const int c = ct * 8 + row;
        *(ulonglong2*)(out + ((size_t)n * CC + c) * SS + sb) = make_ulonglong2(o0, o1);
    }
}

extern "C" void kernel_launch(void* const* d_in, const int* in_sizes, int n_in,
                              void* d_out, int out_size) {
    const float* q = (const float*)d_in[0];
    const float* k = (const float*)d_in[1];
    const float* v = (const float*)d_in[2];
    float* out = (float*)d_out;

    cudaFuncSetAttribute(laplace_attn_kernel,
                         cudaFuncAttributeMaxDynamicSharedMemorySize, SMEM_BYTES);

    laplace_attn_kernel<<<NB * (CC / 8), THREADS, SMEM_BYTES>>>(q, k, v, out);
}

// round 4
// speedup vs baseline: 1.4270x; 1.4270x over previous
#include <cuda_runtime.h>

#define NB      2
#define CC      512
#define SS      256
#define DCHUNK  32
#define NCHUNK  (CC / DCHUNK)     // 16
#define THREADS 512
#define WARPS   16

// smem (floats): ks/vs double-buffered: 4*DCHUNK*SS = 32768 floats (131072 B)
// rw (per-warp reduce scratch): WARPS * 16 * 33 = 8448 floats (33792 B)
#define KS_FLOATS   (2 * DCHUNK * SS)
#define SMEM_FLOATS (4 * DCHUNK * SS + WARPS * 16 * 33)
#define SMEM_BYTES  (SMEM_FLOATS * 4)

typedef unsigned long long ull;

__device__ __forceinline__ ull add2(ull a, ull b) {
    ull c; asm("add.rn.f32x2 %0, %1, %2;" : "=l"(c) : "l"(a), "l"(b)); return c;
}
__device__ __forceinline__ ull mul2(ull a, ull b) {
    ull c; asm("mul.rn.f32x2 %0, %1, %2;" : "=l"(c) : "l"(a), "l"(b)); return c;
}
__device__ __forceinline__ ull fma2(ull a, ull b, ull c) {
    ull d; asm("fma.rn.f32x2 %0, %1, %2, %3;" : "=l"(d) : "l"(a), "l"(b), "l"(c)); return d;
}
__device__ __forceinline__ ull abs2(ull a) {
    return a & 0x7FFFFFFF7FFFFFFFULL;           // 2x LOP3 on the ALU pipe
}
__device__ __forceinline__ ull pack2(float x, float y) {
    ull r; asm("mov.b64 %0, {%1, %2};" : "=l"(r) : "f"(x), "f"(y)); return r;
}
__device__ __forceinline__ ull dup2(float x) { return pack2(x, x); }
__device__ __forceinline__ float hadd2(ull a) {
    float lo = __uint_as_float((unsigned)a);
    float hi = __uint_as_float((unsigned)(a >> 32));
    return lo + hi;
}
__device__ __forceinline__ void cp_async16(void* sdst, const void* gsrc) {
    unsigned a = (unsigned)__cvta_generic_to_shared(sdst);
    asm volatile("cp.async.cg.shared.global [%0], [%1], 16;\n" :: "r"(a), "l"(gsrc));
}

extern __shared__ __align__(16) float smem[];

__device__ __forceinline__ void stage_chunk(const float* kg, const float* vg,
                                            float* kd, float* vd, int tid) {
    const float4* kg4 = (const float4*)kg;
    const float4* vg4 = (const float4*)vg;
#pragma unroll
    for (int j = 0; j < 4; j++) {               // 2048 float4 per tensor / 512 thr
        int idx = tid + j * THREADS;
        cp_async16(kd + idx * 4, kg4 + idx);
        cp_async16(vd + idx * 4, vg4 + idx);
    }
    asm volatile("cp.async.commit_group;\n" ::: "memory");
}

__global__ void __launch_bounds__(THREADS, 1)
laplace_attn_kernel(const float* __restrict__ q,
                    const float* __restrict__ k,
                    const float* __restrict__ v,
                    float* __restrict__ out)
{
    float* ks  = smem;                           // [2][DCHUNK][SS]
    float* vs  = smem + KS_FLOATS;               // [2][DCHUNK][SS]
    float* rwb = smem + 4 * DCHUNK * SS;         // [WARPS][16][33]

    const int tid = threadIdx.x;
    const int w   = tid >> 5;
    const int l   = tid & 31;
    const int g   = w & 1;                       // row-group (4 rows each)
    const int ds  = w >> 1;                      // d-split 0..7 (4 d's per 32-chunk)
    const int n   = blockIdx.x / (CC / 8);
    const int ct  = blockIdx.x % (CC / 8);
    const int c0  = ct * 8 + g * 4;              // first of this warp's 4 rows

    float* rw = rwb + w * (16 * 33);

    // Lane's s-slice: {4l..4l+3} and {128+4l..128+4l+3} (lane-contiguous
    // float4 blocks -> every smem LDS.128 is bank-conflict-free).
    ull nq[4][4];
#pragma unroll
    for (int r = 0; r < 4; r++) {
        const float* qp = q + ((size_t)n * CC + c0 + r) * SS;
        float4 a = *(const float4*)(qp + 4 * l);
        float4 b = *(const float4*)(qp + 128 + 4 * l);
        nq[r][0] = pack2(-a.x, -a.y);
        nq[r][1] = pack2(-a.z, -a.w);
        nq[r][2] = pack2(-b.x, -b.y);
        nq[r][3] = pack2(-b.z, -b.w);
    }

    const float* kbase = k + (size_t)n * CC * SS;
    const float* vbase = v + (size_t)n * CC * SS;

    ull acc[4][4];
#pragma unroll
    for (int r = 0; r < 4; r++)
#pragma unroll
        for (int j = 0; j < 4; j++) acc[r][j] = 0ULL;

    float m_own = -1e30f;                        // lane's row = (l&15)>>2
    float lsum_own = 0.f;

    stage_chunk(kbase, vbase, ks, vs, tid);      // chunk 0 -> buffer 0

#pragma unroll 1
    for (int ch = 0; ch < NCHUNK; ch++) {
        const int p = ch & 1;
        if (ch + 1 < NCHUNK) {
            stage_chunk(kbase + (size_t)(ch + 1) * DCHUNK * SS,
                        vbase + (size_t)(ch + 1) * DCHUNK * SS,
                        ks + (1 - p) * DCHUNK * SS,
                        vs + (1 - p) * DCHUNK * SS, tid);
            asm volatile("cp.async.wait_group 1;\n" ::: "memory");
        } else {
            asm volatile("cp.async.wait_group 0;\n" ::: "memory");
        }
        __syncthreads();

        const float* kc = ks + p * DCHUNK * SS;
        const float* vc = vs + p * DCHUNK * SS;

        // ---- distance partials: 4 d's x 4 rows, packed f32x2, straight
        //      to per-warp smem scratch (no big live register array) ----
#pragma unroll
        for (int dl = 0; dl < 4; dl++) {
            const int d = ds * 4 + dl;
            const ulonglong2 ka = *(const ulonglong2*)(kc + d * SS + 4 * l);
            const ulonglong2 kb = *(const ulonglong2*)(kc + d * SS + 128 + 4 * l);
#pragma unroll
            for (int r = 0; r < 4; r++) {
                ull t0 = abs2(add2(ka.x, nq[r][0]));
                ull t1 = abs2(add2(ka.y, nq[r][1]));
                ull t2 = abs2(add2(kb.x, nq[r][2]));
                ull t3 = abs2(add2(kb.y, nq[r][3]));
                rw[(r * 4 + dl) * 33 + l] = hadd2(add2(add2(t0, t1), add2(t2, t3)));
            }
        }
        __syncwarp();

        // ---- transpose-reduce: lane pair per (row,d) entry ----
        const int e = l & 15;                    // e = row*4 + dl
        const int h = l >> 4;
        const float* rr = rw + e * 33 + h * 16;
        float s0 = 0.f, s1 = 0.f, s2 = 0.f, s3 = 0.f;
#pragma unroll
        for (int j = 0; j < 16; j += 4) {
            s0 += rr[j + 0]; s1 += rr[j + 1];
            s2 += rr[j + 2]; s3 += rr[j + 3];
        }
        float dist = (s0 + s1) + (s2 + s3);
        dist += __shfl_xor_sync(0xffffffffu, dist, 16);
        const float wv = -0.5f * dist;           // logits = -dist/SCALE, SCALE=2

        // ---- per-warp online softmax over this warp's 4-d segment ----
        float cm = wv;
        cm = fmaxf(cm, __shfl_xor_sync(0xffffffffu, cm, 1));
        cm = fmaxf(cm, __shfl_xor_sync(0xffffffffu, cm, 2));
        const float mnew = fmaxf(m_own, cm);
        const float corr = __expf(m_own - mnew);
        const float pv   = __expf(wv - mnew);
        float ps = pv + __shfl_xor_sync(0xffffffffu, pv, 1);
        ps += __shfl_xor_sync(0xffffffffu, ps, 2);
        lsum_own = lsum_own * corr + ps;
        m_own = mnew;
#pragma unroll
        for (int r = 0; r < 4; r++) {
            const float cr = __shfl_sync(0xffffffffu, corr, r * 4);
            const ull c2 = dup2(cr);
#pragma unroll
            for (int j = 0; j < 4; j++) acc[r][j] = mul2(acc[r][j], c2);
        }

        // ---- P @ V: packed FMA, p broadcast via shfl ----
#pragma unroll
        for (int dl = 0; dl < 4; dl++) {
            const int d = ds * 4 + dl;
            const ulonglong2 va = *(const ulonglong2*)(vc + d * SS + 4 * l);
            const ulonglong2 vb = *(const ulonglong2*)(vc + d * SS + 128 + 4 * l);
#pragma unroll
            for (int r = 0; r < 4; r++) {
                const float pj = __shfl_sync(0xffffffffu, pv, r * 4 + dl);
                const ull p2 = dup2(pj);
                acc[r][0] = fma2(p2, va.x, acc[r][0]);
                acc[r][1] = fma2(p2, va.y, acc[r][1]);
                acc[r][2] = fma2(p2, vb.x, acc[r][2]);
                acc[r][3] = fma2(p2, vb.y, acc[r][3]);
            }
        }
        __syncthreads();                         // buffer p reusable
    }

    // ================= epilogue: merge the 8 d-split segments =================
    float* accbuf = smem;                        // [8 rows][8 splits][256] (reuses ks)
    float* stats  = smem + 8 * 8 * 256;          // [8 rows][8 splits][2]  (reuses vs)

#pragma unroll
    for (int r = 0; r < 4; r++) {
        const int row = g * 4 + r;
        float* dst = accbuf + (row * 8 + ds) * 256;
        *(ulonglong2*)(dst + 4 * l)       = make_ulonglong2(acc[r][0], acc[r][1]);
        *(ulonglong2*)(dst + 128 + 4 * l) = make_ulonglong2(acc[r][2], acc[r][3]);
    }
    if (l < 16 && (l & 3) == 0) {
        const int row = g * 4 + (l >> 2);
        stats[(row * 8 + ds) * 2 + 0] = m_own;
        stats[(row * 8 + ds) * 2 + 1] = lsum_own;
    }
    __syncthreads();

    {
        const int row  = w >> 1;
        const int half = w & 1;
        const int sb   = half * 128 + l * 4;

        float M = -1e30f;
#pragma unroll
        for (int i = 0; i < 8; i++) M = fmaxf(M, stats[(row * 8 + i) * 2]);

        float L = 0.f;
        ull o0 = 0ULL, o1 = 0ULL;
#pragma unroll
        for (int i = 0; i < 8; i++) {
            const float sc = __expf(stats[(row * 8 + i) * 2] - M);
            L += stats[(row * 8 + i) * 2 + 1] * sc;
            const ulonglong2 a = *(const ulonglong2*)(accbuf + (row * 8 + i) * 256 + sb);
            const ull s2 = dup2(sc);
            o0 = fma2(s2, a.x, o0);
            o1 = fma2(s2, a.y, o1);
        }
        const ull i2 = dup2(1.f / L);
        o0 = mul2(o0, i2);
        o1 = mul2(o1, i2);

        const int c = ct * 8 + row;
        *(ulonglong2*)(out + ((size_t)n * CC + c) * SS + sb) = make_ulonglong2(o0, o1);
    }
}

extern "C" void kernel_launch(void* const* d_in, const int* in_sizes, int n_in,
                              void* d_out, int out_size) {
    const float* q = (const float*)d_in[0];
    const float* k = (const float*)d_in[1];
    const float* v = (const float*)d_in[2];
    float* out = (float*)d_out;

    cudaFuncSetAttribute(laplace_attn_kernel,
                         cudaFuncAttributeMaxDynamicSharedMemorySize, SMEM_BYTES);

    laplace_attn_kernel<<<NB * (CC / 8), THREADS, SMEM_BYTES>>>(q, k, v, out);
}

// round 5
// speedup vs baseline: 1.5135x; 1.0606x over previous
#include <cuda_runtime.h>

#define NB      2
#define CC      512
#define SS      256
#define DCHUNK  32
#define NCHUNK  (CC / DCHUNK)     // 16
#define THREADS 512
#define WARPS   16

#define CHUNK_BYTES (DCHUNK * SS * 4)            // 32768 per tensor per chunk

// smem (floats): ks/vs double-buffered: 4*DCHUNK*SS = 32768 floats (131072 B)
// rw (per-warp reduce scratch): WARPS * 16 * 33 = 8448 floats (33792 B)
// mbar: 2 x 8 B
#define KS_FLOATS   (2 * DCHUNK * SS)
#define RW_OFF      (4 * DCHUNK * SS)
#define MBAR_OFF    (RW_OFF + WARPS * 16 * 33)   // float index, 8B-aligned (even)
#define SMEM_BYTES  ((MBAR_OFF + 4) * 4)

typedef unsigned long long ull;

__device__ __forceinline__ ull add2(ull a, ull b) {
    ull c; asm("add.rn.f32x2 %0, %1, %2;" : "=l"(c) : "l"(a), "l"(b)); return c;
}
__device__ __forceinline__ ull mul2(ull a, ull b) {
    ull c; asm("mul.rn.f32x2 %0, %1, %2;" : "=l"(c) : "l"(a), "l"(b)); return c;
}
__device__ __forceinline__ ull fma2(ull a, ull b, ull c) {
    ull d; asm("fma.rn.f32x2 %0, %1, %2, %3;" : "=l"(d) : "l"(a), "l"(b), "l"(c)); return d;
}
__device__ __forceinline__ ull abs2(ull a) {
    return a & 0x7FFFFFFF7FFFFFFFULL;            // 2x LOP3 on the ALU pipe
}
__device__ __forceinline__ ull pack2(float x, float y) {
    ull r; asm("mov.b64 %0, {%1, %2};" : "=l"(r) : "f"(x), "f"(y)); return r;
}
__device__ __forceinline__ ull dup2(float x) { return pack2(x, x); }
__device__ __forceinline__ float hadd2(ull a) {
    float lo = __uint_as_float((unsigned)a);
    float hi = __uint_as_float((unsigned)(a >> 32));
    return lo + hi;
}

// ---- TMA bulk staging (one instruction per 32KB chunk) ----
__device__ __forceinline__ void bulk_g2s(void* sdst, const void* gsrc,
                                         unsigned bytes, unsigned mbar) {
    unsigned d = (unsigned)__cvta_generic_to_shared(sdst);
    asm volatile(
        "cp.async.bulk.shared::cluster.global.mbarrier::complete_tx::bytes "
        "[%0], [%1], %2, [%3];"
        :: "r"(d), "l"(gsrc), "r"(bytes), "r"(mbar) : "memory");
}
__device__ __forceinline__ void mbar_init(unsigned mbar, unsigned count) {
    asm volatile("mbarrier.init.shared.b64 [%0], %1;" :: "r"(mbar), "r"(count) : "memory");
}
__device__ __forceinline__ void mbar_expect_tx(unsigned mbar, unsigned bytes) {
    asm volatile("mbarrier.arrive.expect_tx.shared.b64 _, [%0], %1;"
                 :: "r"(mbar), "r"(bytes) : "memory");
}
__device__ __forceinline__ void mbar_wait(unsigned mbar, unsigned parity) {
    asm volatile(
        "{\n\t"
        ".reg .pred P;\n\t"
        "W%=:\n\t"
        "mbarrier.try_wait.parity.acquire.cta.shared::cta.b64 P, [%0], %1, 0x989680;\n\t"
        "@!P bra W%=;\n\t"
        "}"
        :: "r"(mbar), "r"(parity) : "memory");
}

extern __shared__ __align__(16) float smem[];

__global__ void __launch_bounds__(THREADS, 1)
laplace_attn_kernel(const float* __restrict__ q,
                    const float* __restrict__ k,
                    const float* __restrict__ v,
                    float* __restrict__ out)
{
    float* ks  = smem;                           // [2][DCHUNK][SS]
    float* vs  = smem + KS_FLOATS;               // [2][DCHUNK][SS]
    float* rwb = smem + RW_OFF;                  // [WARPS][16][33]
    const unsigned mbar0 =
        (unsigned)__cvta_generic_to_shared(smem + MBAR_OFF);   // 2 mbarriers, 8B each

    const int tid = threadIdx.x;
    const int w   = tid >> 5;
    const int l   = tid & 31;
    const int g   = w & 1;                       // row-group (4 rows each)
    const int ds  = w >> 1;                      // d-split 0..7 (4 d's per 32-chunk)
    const int n   = blockIdx.x / (CC / 8);
    const int ct  = blockIdx.x % (CC / 8);
    const int c0  = ct * 8 + g * 4;              // first of this warp's 4 rows

    float* rw = rwb + w * (16 * 33);

    const float* kbase = k + (size_t)n * CC * SS;
    const float* vbase = v + (size_t)n * CC * SS;

    // init mbarriers and kick off chunk 0 before the (long) q register load
    if (tid == 0) {
        mbar_init(mbar0, 1);
        mbar_init(mbar0 + 8, 1);
        asm volatile("fence.proxy.async.shared::cta;" ::: "memory");
        mbar_expect_tx(mbar0, 2 * CHUNK_BYTES);
        bulk_g2s(ks, kbase, CHUNK_BYTES, mbar0);
        bulk_g2s(vs, vbase, CHUNK_BYTES, mbar0);
    }

    // Lane's s-slice: {4l..4l+3} and {128+4l..128+4l+3} (lane-contiguous
    // float4 blocks -> every smem LDS.128 is bank-conflict-free).
    ull nq[4][4];
#pragma unroll
    for (int r = 0; r < 4; r++) {
        const float* qp = q + ((size_t)n * CC + c0 + r) * SS;
        float4 a = *(const float4*)(qp + 4 * l);
        float4 b = *(const float4*)(qp + 128 + 4 * l);
        nq[r][0] = pack2(-a.x, -a.y);
        nq[r][1] = pack2(-a.z, -a.w);
        nq[r][2] = pack2(-b.x, -b.y);
        nq[r][3] = pack2(-b.z, -b.w);
    }

    ull acc[4][4];
#pragma unroll
    for (int r = 0; r < 4; r++)
#pragma unroll
        for (int j = 0; j < 4; j++) acc[r][j] = 0ULL;

    float m_own = -1e30f;                        // lane's row = (l&15)>>2
    float lsum_own = 0.f;

    __syncthreads();   // mbarrier init visible to all before any wait

#pragma unroll 1
    for (int ch = 0; ch < NCHUNK; ch++) {
        const int p = ch & 1;

        // issue next chunk into the other buffer (its consumers finished at
        // the trailing __syncthreads of iteration ch-1)
        if (ch + 1 < NCHUNK && tid == 0) {
            const unsigned mb = mbar0 + 8u * (1 - p);
            mbar_expect_tx(mb, 2 * CHUNK_BYTES);
            bulk_g2s(ks + (1 - p) * DCHUNK * SS,
                     kbase + (size_t)(ch + 1) * DCHUNK * SS, CHUNK_BYTES, mb);
            bulk_g2s(vs + (1 - p) * DCHUNK * SS,
                     vbase + (size_t)(ch + 1) * DCHUNK * SS, CHUNK_BYTES, mb);
        }

        // wait for this chunk's data (buffer p, use-count parity)
        mbar_wait(mbar0 + 8u * p, (unsigned)((ch >> 1) & 1));

        const float* kc = ks + p * DCHUNK * SS;
        const float* vc = vs + p * DCHUNK * SS;

        // ---- distance partials: 4 d's x 4 rows, packed f32x2 ----
#pragma unroll
        for (int dl = 0; dl < 4; dl++) {
            const int d = ds * 4 + dl;
            const ulonglong2 ka = *(const ulonglong2*)(kc + d * SS + 4 * l);
            const ulonglong2 kb = *(const ulonglong2*)(kc + d * SS + 128 + 4 * l);
#pragma unroll
            for (int r = 0; r < 4; r++) {
                ull t0 = abs2(add2(ka.x, nq[r][0]));
                ull t1 = abs2(add2(ka.y, nq[r][1]));
                ull t2 = abs2(add2(kb.x, nq[r][2]));
                ull t3 = abs2(add2(kb.y, nq[r][3]));
                rw[(r * 4 + dl) * 33 + l] = hadd2(add2(add2(t0, t1), add2(t2, t3)));
            }
        }
        __syncwarp();

        // ---- transpose-reduce: lane pair per (row,d) entry ----
        const int e = l & 15;                    // e = row*4 + dl
        const int h = l >> 4;
        const float* rr = rw + e * 33 + h * 16;
        float s0 = 0.f, s1 = 0.f, s2 = 0.f, s3 = 0.f;
#pragma unroll
        for (int j = 0; j < 16; j += 4) {
            s0 += rr[j + 0]; s1 += rr[j + 1];
            s2 += rr[j + 2]; s3 += rr[j + 3];
        }
        float dist = (s0 + s1) + (s2 + s3);
        dist += __shfl_xor_sync(0xffffffffu, dist, 16);
        const float wv = -0.5f * dist;           // logits = -dist/SCALE, SCALE=2

        // ---- per-warp online softmax over this warp's 4-d segment ----
        float cm = wv;
        cm = fmaxf(cm, __shfl_xor_sync(0xffffffffu, cm, 1));
        cm = fmaxf(cm, __shfl_xor_sync(0xffffffffu, cm, 2));
        const float mnew = fmaxf(m_own, cm);
        const float corr = __expf(m_own - mnew);
        const float pv   = __expf(wv - mnew);
        float ps = pv + __shfl_xor_sync(0xffffffffu, pv, 1);
        ps += __shfl_xor_sync(0xffffffffu, ps, 2);
        lsum_own = lsum_own * corr + ps;
        m_own = mnew;
#pragma unroll
        for (int r = 0; r < 4; r++) {
            const float cr = __shfl_sync(0xffffffffu, corr, r * 4);
            const ull c2 = dup2(cr);
#pragma unroll
            for (int j = 0; j < 4; j++) acc[r][j] = mul2(acc[r][j], c2);
        }

        // ---- P @ V: packed FMA, p broadcast via shfl ----
#pragma unroll
        for (int dl = 0; dl < 4; dl++) {
            const int d = ds * 4 + dl;
            const ulonglong2 va = *(const ulonglong2*)(vc + d * SS + 4 * l);
            const ulonglong2 vb = *(const ulonglong2*)(vc + d * SS + 128 + 4 * l);
#pragma unroll
            for (int r = 0; r < 4; r++) {
                const float pj = __shfl_sync(0xffffffffu, pv, r * 4 + dl);
                const ull p2 = dup2(pj);
                acc[r][0] = fma2(p2, va.x, acc[r][0]);
                acc[r][1] = fma2(p2, va.y, acc[r][1]);
                acc[r][2] = fma2(p2, vb.x, acc[r][2]);
                acc[r][3] = fma2(p2, vb.y, acc[r][3]);
            }
        }
        __syncthreads();                         // buffer p reusable for TMA
    }

    // ================= epilogue: merge the 8 d-split segments =================
    float* accbuf = smem;                        // [8 rows][8 splits][256] (reuses ks)
    float* stats  = smem + 8 * 8 * 256;          // [8 rows][8 splits][2]  (reuses vs)

#pragma unroll
    for (int r = 0; r < 4; r++) {
        const int row = g * 4 + r;
        float* dst = accbuf + (row * 8 + ds) * 256;
        *(ulonglong2*)(dst + 4 * l)       = make_ulonglong2(acc[r][0], acc[r][1]);
        *(ulonglong2*)(dst + 128 + 4 * l) = make_ulonglong2(acc[r][2], acc[r][3]);
    }
    if (l < 16 && (l & 3) == 0) {
        const int row = g * 4 + (l >> 2);
        stats[(row * 8 + ds) * 2 + 0] = m_own;
        stats[(row * 8 + ds) * 2 + 1] = lsum_own;
    }
    __syncthreads();

    {
        const int row  = w >> 1;
        const int half = w & 1;
        const int sb   = half * 128 + l * 4;

        float M = -1e30f;
#pragma unroll
        for (int i = 0; i < 8; i++) M = fmaxf(M, stats[(row * 8 + i) * 2]);

        float L = 0.f;
        ull o0 = 0ULL, o1 = 0ULL;
#pragma unroll
        for (int i = 0; i < 8; i++) {
            const float sc = __expf(stats[(row * 8 + i) * 2] - M);
            L += stats[(row * 8 + i) * 2 + 1] * sc;
            const ulonglong2 a = *(const ulonglong2*)(accbuf + (row * 8 + i) * 256 + sb);
            const ull s2 = dup2(sc);
            o0 = fma2(s2, a.x, o0);
            o1 = fma2(s2, a.y, o1);
        }
        const ull i2 = dup2(1.f / L);
        o0 = mul2(o0, i2);
        o1 = mul2(o1, i2);

        const int c = ct * 8 + row;
        *(ulonglong2*)(out + ((size_t)n * CC + c) * SS + sb) = make_ulonglong2(o0, o1);
    }
}

extern "C" void kernel_launch(void* const* d_in, const int* in_sizes, int n_in,
                              void* d_out, int out_size) {
    const float* q = (const float*)d_in[0];
    const float* k = (const float*)d_in[1];
    const float* v = (const float*)d_in[2];
    float* out = (float*)d_out;

    cudaFuncSetAttribute(laplace_attn_kernel,
                         cudaFuncAttributeMaxDynamicSharedMemorySize, SMEM_BYTES);

    laplace_attn_kernel<<<NB * (CC / 8), THREADS, SMEM_BYTES>>>(q, k, v, out);
}

// round 6
// speedup vs baseline: 1.7127x; 1.1317x over previous
#include <cuda_runtime.h>

#define NB      2
#define CC      512
#define SS      256
#define DCHUNK  32
#define NCHUNK  (CC / DCHUNK)     // 16
#define THREADS 512
#define WARPS   16

#define CHUNK_BYTES (DCHUNK * SS * 4)            // 32768 per tensor per chunk

// smem (floats): ks/vs double-buffered: 4*DCHUNK*SS = 32768 floats (131072 B)
// rw (per-warp reduce scratch): WARPS * 16 * 33 = 8448 floats (33792 B)
// mbar: 2 x 8 B
#define KS_FLOATS   (2 * DCHUNK * SS)
#define RW_OFF      (4 * DCHUNK * SS)
#define MBAR_OFF    (RW_OFF + WARPS * 16 * 33)   // float index, 8B-aligned (even)
#define SMEM_BYTES  ((MBAR_OFF + 4) * 4)

typedef unsigned long long ull;

__device__ __forceinline__ ull add2(ull a, ull b) {
    ull c; asm("add.rn.f32x2 %0, %1, %2;" : "=l"(c) : "l"(a), "l"(b)); return c;
}
__device__ __forceinline__ ull mul2(ull a, ull b) {
    ull c; asm("mul.rn.f32x2 %0, %1, %2;" : "=l"(c) : "l"(a), "l"(b)); return c;
}
__device__ __forceinline__ ull fma2(ull a, ull b, ull c) {
    ull d; asm("fma.rn.f32x2 %0, %1, %2, %3;" : "=l"(d) : "l"(a), "l"(b), "l"(c)); return d;
}
__device__ __forceinline__ ull pack2(float x, float y) {
    ull r; asm("mov.b64 %0, {%1, %2};" : "=l"(r) : "f"(x), "f"(y)); return r;
}
__device__ __forceinline__ ull dup2(float x) { return pack2(x, x); }
__device__ __forceinline__ float2 unpack2f(ull a) {
    float2 r; asm("mov.b64 {%0, %1}, %2;" : "=f"(r.x), "=f"(r.y) : "l"(a)); return r;
}

// ---- TMA bulk staging (one instruction per 32KB chunk) ----
__device__ __forceinline__ void bulk_g2s(void* sdst, const void* gsrc,
                                         unsigned bytes, unsigned mbar) {
    unsigned d = (unsigned)__cvta_generic_to_shared(sdst);
    asm volatile(
        "cp.async.bulk.shared::cluster.global.mbarrier::complete_tx::bytes "
        "[%0], [%1], %2, [%3];"
        :: "r"(d), "l"(gsrc), "r"(bytes), "r"(mbar) : "memory");
}
__device__ __forceinline__ void mbar_init(unsigned mbar, unsigned count) {
    asm volatile("mbarrier.init.shared.b64 [%0], %1;" :: "r"(mbar), "r"(count) : "memory");
}
__device__ __forceinline__ void mbar_expect_tx(unsigned mbar, unsigned bytes) {
    asm volatile("mbarrier.arrive.expect_tx.shared.b64 _, [%0], %1;"
                 :: "r"(mbar), "r"(bytes) : "memory");
}
__device__ __forceinline__ void mbar_wait(unsigned mbar, unsigned parity) {
    asm volatile(
        "{\n\t"
        ".reg .pred P;\n\t"
        "W%=:\n\t"
        "mbarrier.try_wait.parity.acquire.cta.shared::cta.b64 P, [%0], %1, 0x989680;\n\t"
        "@!P bra W%=;\n\t"
        "}"
        :: "r"(mbar), "r"(parity) : "memory");
}

extern __shared__ __align__(16) float smem[];

__global__ void __launch_bounds__(THREADS, 1)
laplace_attn_kernel(const float* __restrict__ q,
                    const float* __restrict__ k,
                    const float* __restrict__ v,
                    float* __restrict__ out)
{
    float* ks  = smem;                           // [2][DCHUNK][SS]
    float* vs  = smem + KS_FLOATS;               // [2][DCHUNK][SS]
    float* rwb = smem + RW_OFF;                  // [WARPS][16][33]
    const unsigned mbar0 =
        (unsigned)__cvta_generic_to_shared(smem + MBAR_OFF);   // 2 mbarriers, 8B each

    const int tid = threadIdx.x;
    const int w   = tid >> 5;
    const int l   = tid & 31;
    const int g   = w & 1;                       // row-group (4 rows each)
    const int ds  = w >> 1;                      // d-split 0..7 (4 d's per 32-chunk)
    const int n   = blockIdx.x / (CC / 8);
    const int ct  = blockIdx.x % (CC / 8);
    const int c0  = ct * 8 + g * 4;              // first of this warp's 4 rows

    float* rw = rwb + w * (16 * 33);

    const float* kbase = k + (size_t)n * CC * SS;
    const float* vbase = v + (size_t)n * CC * SS;

    // init mbarriers and kick off chunk 0 before the (long) q register load
    if (tid == 0) {
        mbar_init(mbar0, 1);
        mbar_init(mbar0 + 8, 1);
        asm volatile("fence.proxy.async.shared::cta;" ::: "memory");
        mbar_expect_tx(mbar0, 2 * CHUNK_BYTES);
        bulk_g2s(ks, kbase, CHUNK_BYTES, mbar0);
        bulk_g2s(vs, vbase, CHUNK_BYTES, mbar0);
    }

    // Lane's s-slice: {4l..4l+3} and {128+4l..128+4l+3} (lane-contiguous
    // float4 blocks -> every smem LDS.128 is bank-conflict-free).
    ull nq[4][4];
#pragma unroll
    for (int r = 0; r < 4; r++) {
        const float* qp = q + ((size_t)n * CC + c0 + r) * SS;
        float4 a = *(const float4*)(qp + 4 * l);
        float4 b = *(const float4*)(qp + 128 + 4 * l);
        nq[r][0] = pack2(-a.x, -a.y);
        nq[r][1] = pack2(-a.z, -a.w);
        nq[r][2] = pack2(-b.x, -b.y);
        nq[r][3] = pack2(-b.z, -b.w);
    }

    ull acc[4][4];
#pragma unroll
    for (int r = 0; r < 4; r++)
#pragma unroll
        for (int j = 0; j < 4; j++) acc[r][j] = 0ULL;

    float m_own = -1e30f;                        // lane's row = (l&15)>>2
    float lsum_own = 0.f;

    __syncthreads();   // mbarrier init visible to all before any wait

#pragma unroll 1
    for (int ch = 0; ch < NCHUNK; ch++) {
        const int p = ch & 1;

        // issue next chunk into the other buffer (its consumers finished at
        // the trailing __syncthreads of iteration ch-1)
        if (ch + 1 < NCHUNK && tid == 0) {
            const unsigned mb = mbar0 + 8u * (1 - p);
            mbar_expect_tx(mb, 2 * CHUNK_BYTES);
            bulk_g2s(ks + (1 - p) * DCHUNK * SS,
                     kbase + (size_t)(ch + 1) * DCHUNK * SS, CHUNK_BYTES, mb);
            bulk_g2s(vs + (1 - p) * DCHUNK * SS,
                     vbase + (size_t)(ch + 1) * DCHUNK * SS, CHUNK_BYTES, mb);
        }

        // wait for this chunk's data (buffer p, use-count parity)
        mbar_wait(mbar0 + 8u * p, (unsigned)((ch >> 1) & 1));

        const float* kc = ks + p * DCHUNK * SS;
        const float* vc = vs + p * DCHUNK * SS;

        // ---- distance partials: packed diffs + scalar FADD with |.|
        //      source modifiers (abs folds into FADD -> no LOP3) ----
#pragma unroll
        for (int dl = 0; dl < 4; dl++) {
            const int d = ds * 4 + dl;
            const ulonglong2 ka = *(const ulonglong2*)(kc + d * SS + 4 * l);
            const ulonglong2 kb = *(const ulonglong2*)(kc + d * SS + 128 + 4 * l);
#pragma unroll
            for (int r = 0; r < 4; r++) {
                const float2 f0 = unpack2f(add2(ka.x, nq[r][0]));
                const float2 f1 = unpack2f(add2(ka.y, nq[r][1]));
                const float2 f2 = unpack2f(add2(kb.x, nq[r][2]));
                const float2 f3 = unpack2f(add2(kb.y, nq[r][3]));
                const float s0 = fabsf(f0.x) + fabsf(f0.y);
                const float s1 = fabsf(f1.x) + fabsf(f1.y);
                const float s2 = fabsf(f2.x) + fabsf(f2.y);
                const float s3 = fabsf(f3.x) + fabsf(f3.y);
                rw[(r * 4 + dl) * 33 + l] = (s0 + s1) + (s2 + s3);
            }
        }
        __syncwarp();

        // ---- transpose-reduce: lane pair per (row,d) entry ----
        const int e = l & 15;                    // e = row*4 + dl
        const int h = l >> 4;
        const float* rr = rw + e * 33 + h * 16;
        float s0 = 0.f, s1 = 0.f, s2 = 0.f, s3 = 0.f;
#pragma unroll
        for (int j = 0; j < 16; j += 4) {
            s0 += rr[j + 0]; s1 += rr[j + 1];
            s2 += rr[j + 2]; s3 += rr[j + 3];
        }
        float dist = (s0 + s1) + (s2 + s3);
        dist += __shfl_xor_sync(0xffffffffu, dist, 16);
        const float wv = -0.5f * dist;           // logits = -dist/SCALE, SCALE=2

        // ---- per-warp online softmax; rescale only when max improves ----
        float cm = wv;
        cm = fmaxf(cm, __shfl_xor_sync(0xffffffffu, cm, 1));
        cm = fmaxf(cm, __shfl_xor_sync(0xffffffffu, cm, 2));
        if (__any_sync(0xffffffffu, cm > m_own)) {
            const float mnew = fmaxf(m_own, cm);
            const float corr = __expf(m_own - mnew);
            m_own = mnew;
            lsum_own *= corr;
#pragma unroll
            for (int r = 0; r < 4; r++) {
                const float cr = __shfl_sync(0xffffffffu, corr, r * 4);
                const ull c2 = dup2(cr);
#pragma unroll
                for (int j = 0; j < 4; j++) acc[r][j] = mul2(acc[r][j], c2);
            }
        }
        const float pv = __expf(wv - m_own);
        float ps = pv + __shfl_xor_sync(0xffffffffu, pv, 1);
        ps += __shfl_xor_sync(0xffffffffu, ps, 2);
        lsum_own += ps;

        // ---- P @ V: packed FMA, p broadcast via shfl ----
#pragma unroll
        for (int dl = 0; dl < 4; dl++) {
            const int d = ds * 4 + dl;
            const ulonglong2 va = *(const ulonglong2*)(vc + d * SS + 4 * l);
            const ulonglong2 vb = *(const ulonglong2*)(vc + d * SS + 128 + 4 * l);
#pragma unroll
            for (int r = 0; r < 4; r++) {
                const float pj = __shfl_sync(0xffffffffu, pv, r * 4 + dl);
                const ull p2 = dup2(pj);
                acc[r][0] = fma2(p2, va.x, acc[r][0]);
                acc[r][1] = fma2(p2, va.y, acc[r][1]);
                acc[r][2] = fma2(p2, vb.x, acc[r][2]);
                acc[r][3] = fma2(p2, vb.y, acc[r][3]);
            }
        }
        __syncthreads();                         // buffer p reusable for TMA
    }

    // ================= epilogue: merge the 8 d-split segments =================
    float* accbuf = smem;                        // [8 rows][8 splits][256] (reuses ks)
    float* stats  = smem + 8 * 8 * 256;          // [8 rows][8 splits][2]  (reuses vs)

#pragma unroll
    for (int r = 0; r < 4; r++) {
        const int row = g * 4 + r;
        float* dst = accbuf + (row * 8 + ds) * 256;
        *(ulonglong2*)(dst + 4 * l)       = make_ulonglong2(acc[r][0], acc[r][1]);
        *(ulonglong2*)(dst + 128 + 4 * l) = make_ulonglong2(acc[r][2], acc[r][3]);
    }
    if (l < 16 && (l & 3) == 0) {
        const int row = g * 4 + (l >> 2);
        stats[(row * 8 + ds) * 2 + 0] = m_own;
        stats[(row * 8 + ds) * 2 + 1] = lsum_own;
    }
    __syncthreads();

    {
        const int row  = w >> 1;
        const int half = w & 1;
        const int sb   = half * 128 + l * 4;

        float M = -1e30f;
#pragma unroll
        for (int i = 0; i < 8; i++) M = fmaxf(M, stats[(row * 8 + i) * 2]);

        float L = 0.f;
        ull o0 = 0ULL, o1 = 0ULL;
#pragma unroll
        for (int i = 0; i < 8; i++) {
            const float sc = __expf(stats[(row * 8 + i) * 2] - M);
            L += stats[(row * 8 + i) * 2 + 1] * sc;
            const ulonglong2 a = *(const ulonglong2*)(accbuf + (row * 8 + i) * 256 + sb);
            const ull s2 = dup2(sc);
            o0 = fma2(s2, a.x, o0);
            o1 = fma2(s2, a.y, o1);
        }
        const ull i2 = dup2(1.f / L);
        o0 = mul2(o0, i2);
        o1 = mul2(o1, i2);

        const int c = ct * 8 + row;
        *(ulonglong2*)(out + ((size_t)n * CC + c) * SS + sb) = make_ulonglong2(o0, o1);
    }
}

extern "C" void kernel_launch(void* const* d_in, const int* in_sizes, int n_in,
                              void* d_out, int out_size) {
    const float* q = (const float*)d_in[0];
    const float* k = (const float*)d_in[1];
    const float* v = (const float*)d_in[2];
    float* out = (float*)d_out;

    cudaFuncSetAttribute(laplace_attn_kernel,
                         cudaFuncAttributeMaxDynamicSharedMemorySize, SMEM_BYTES);

    laplace_attn_kernel<<<NB * (CC / 8), THREADS, SMEM_BYTES>>>(q, k, v, out);
}

// round 7
// speedup vs baseline: 1.8176x; 1.0612x over previous
#include <cuda_runtime.h>

#define NB      2
#define CC      512
#define SS      256
#define DCHUNK  32
#define NCHUNK  (CC / DCHUNK)     // 16
#define THREADS 512
#define WARPS   16
#define NSTAGE  3

#define CHUNK_BYTES  (DCHUNK * SS * 4)           // 32768 per tensor per chunk
#define STAGE_FLOATS (DCHUNK * SS)               // 8192

// smem (floats):
//  ks: [3][DCHUNK][SS] = 24576 floats
//  vs: [3][DCHUNK][SS] = 24576 floats
//  rw: [WARPS][16][33] =  8448 floats
//  mbar: full[3] + empty[3], 8B each
#define VS_OFF      (NSTAGE * STAGE_FLOATS)
#define RW_OFF      (2 * NSTAGE * STAGE_FLOATS)
#define MBAR_OFF    (RW_OFF + WARPS * 16 * 33)   // float idx, 8B aligned (even)
#define SMEM_BYTES  ((MBAR_OFF + 16) * 4)        // 230464 B

typedef unsigned long long ull;

__device__ __forceinline__ ull add2(ull a, ull b) {
    ull c; asm("add.rn.f32x2 %0, %1, %2;" : "=l"(c) : "l"(a), "l"(b)); return c;
}
__device__ __forceinline__ ull mul2(ull a, ull b) {
    ull c; asm("mul.rn.f32x2 %0, %1, %2;" : "=l"(c) : "l"(a), "l"(b)); return c;
}
__device__ __forceinline__ ull fma2(ull a, ull b, ull c) {
    ull d; asm("fma.rn.f32x2 %0, %1, %2, %3;" : "=l"(d) : "l"(a), "l"(b), "l"(c)); return d;
}
__device__ __forceinline__ ull pack2(float x, float y) {
    ull r; asm("mov.b64 %0, {%1, %2};" : "=l"(r) : "f"(x), "f"(y)); return r;
}
__device__ __forceinline__ ull dup2(float x) { return pack2(x, x); }
__device__ __forceinline__ float2 unpack2f(ull a) {
    float2 r; asm("mov.b64 {%0, %1}, %2;" : "=f"(r.x), "=f"(r.y) : "l"(a)); return r;
}

// ---- TMA bulk staging + mbarrier ring ----
__device__ __forceinline__ void bulk_g2s(void* sdst, const void* gsrc,
                                         unsigned bytes, unsigned mbar) {
    unsigned d = (unsigned)__cvta_generic_to_shared(sdst);
    asm volatile(
        "cp.async.bulk.shared::cluster.global.mbarrier::complete_tx::bytes "
        "[%0], [%1], %2, [%3];"
        :: "r"(d), "l"(gsrc), "r"(bytes), "r"(mbar) : "memory");
}
__device__ __forceinline__ void mbar_init(unsigned mbar, unsigned count) {
    asm volatile("mbarrier.init.shared.b64 [%0], %1;" :: "r"(mbar), "r"(count) : "memory");
}
__device__ __forceinline__ void mbar_expect_tx(unsigned mbar, unsigned bytes) {
    asm volatile("mbarrier.arrive.expect_tx.shared.b64 _, [%0], %1;"
                 :: "r"(mbar), "r"(bytes) : "memory");
}
__device__ __forceinline__ void mbar_arrive(unsigned mbar) {
    asm volatile("mbarrier.arrive.shared.b64 _, [%0];" :: "r"(mbar) : "memory");
}
__device__ __forceinline__ void mbar_wait(unsigned mbar, unsigned parity) {
    asm volatile(
        "{\n\t"
        ".reg .pred P;\n\t"
        "W%=:\n\t"
        "mbarrier.try_wait.parity.acquire.cta.shared::cta.b64 P, [%0], %1, 0x989680;\n\t"
        "@!P bra W%=;\n\t"
        "}"
        :: "r"(mbar), "r"(parity) : "memory");
}

extern __shared__ __align__(16) float smem[];

__global__ void __launch_bounds__(THREADS, 1)
laplace_attn_kernel(const float* __restrict__ q,
                    const float* __restrict__ k,
                    const float* __restrict__ v,
                    float* __restrict__ out)
{
    float* ks  = smem;                           // [3][DCHUNK][SS]
    float* vs  = smem + VS_OFF;                  // [3][DCHUNK][SS]
    float* rwb = smem + RW_OFF;                  // [WARPS][16][33]
    const unsigned mb_full  = (unsigned)__cvta_generic_to_shared(smem + MBAR_OFF);
    const unsigned mb_empty = mb_full + 8u * NSTAGE;

    const int tid = threadIdx.x;
    const int w   = tid >> 5;
    const int l   = tid & 31;
    const int g   = w & 1;                       // row-group (4 rows each)
    const int ds  = w >> 1;                      // d-split 0..7 (4 d's per 32-chunk)
    const int n   = blockIdx.x / (CC / 8);
    const int ct  = blockIdx.x % (CC / 8);
    const int c0  = ct * 8 + g * 4;              // first of this warp's 4 rows

    float* rw = rwb + w * (16 * 33);

    const float* kbase = k + (size_t)n * CC * SS;
    const float* vbase = v + (size_t)n * CC * SS;

    // init barriers + fill all 3 stages (chunks 0..2)
    if (tid == 0) {
#pragma unroll
        for (int s = 0; s < NSTAGE; s++) {
            mbar_init(mb_full  + 8u * s, 1);
            mbar_init(mb_empty + 8u * s, WARPS);
        }
        asm volatile("fence.proxy.async.shared::cta;" ::: "memory");
#pragma unroll
        for (int s = 0; s < NSTAGE; s++) {
            mbar_expect_tx(mb_full + 8u * s, 2 * CHUNK_BYTES);
            bulk_g2s(ks + s * STAGE_FLOATS, kbase + (size_t)s * STAGE_FLOATS,
                     CHUNK_BYTES, mb_full + 8u * s);
            bulk_g2s(vs + s * STAGE_FLOATS, vbase + (size_t)s * STAGE_FLOATS,
                     CHUNK_BYTES, mb_full + 8u * s);
        }
    }

    // Lane's s-slice: {4l..4l+3} and {128+4l..128+4l+3} (lane-contiguous
    // float4 blocks -> every smem LDS.128 is bank-conflict-free).
    ull nq[4][4];
#pragma unroll
    for (int r = 0; r < 4; r++) {
        const float* qp = q + ((size_t)n * CC + c0 + r) * SS;
        float4 a = *(const float4*)(qp + 4 * l);
        float4 b = *(const float4*)(qp + 128 + 4 * l);
        nq[r][0] = pack2(-a.x, -a.y);
        nq[r][1] = pack2(-a.z, -a.w);
        nq[r][2] = pack2(-b.x, -b.y);
        nq[r][3] = pack2(-b.z, -b.w);
    }

    ull acc[4][4];
#pragma unroll
    for (int r = 0; r < 4; r++)
#pragma unroll
        for (int j = 0; j < 4; j++) acc[r][j] = 0ULL;

    float m_own = -1e30f;                        // lane's row = (l&15)>>2
    float lsum_own = 0.f;

    __syncthreads();   // barrier init visible before any wait

    int st = 0;        // ring stage = ch % 3
    int rnd = 0;       // ring round = ch / 3

#pragma unroll 1
    for (int ch = 0; ch < NCHUNK; ch++) {
        // wait for this chunk's data
        mbar_wait(mb_full + 8u * st, (unsigned)(rnd & 1));

        const float* kc = ks + st * STAGE_FLOATS;
        const float* vc = vs + st * STAGE_FLOATS;

        // ---- distance partials: packed diffs + FADD with |.| modifiers ----
#pragma unroll
        for (int dl = 0; dl < 4; dl++) {
            const int d = ds * 4 + dl;
            const ulonglong2 ka = *(const ulonglong2*)(kc + d * SS + 4 * l);
            const ulonglong2 kb = *(const ulonglong2*)(kc + d * SS + 128 + 4 * l);
#pragma unroll
            for (int r = 0; r < 4; r++) {
                const float2 f0 = unpack2f(add2(ka.x, nq[r][0]));
                const float2 f1 = unpack2f(add2(ka.y, nq[r][1]));
                const float2 f2 = unpack2f(add2(kb.x, nq[r][2]));
                const float2 f3 = unpack2f(add2(kb.y, nq[r][3]));
                const float s0 = fabsf(f0.x) + fabsf(f0.y);
                const float s1 = fabsf(f1.x) + fabsf(f1.y);
                const float s2 = fabsf(f2.x) + fabsf(f2.y);
                const float s3 = fabsf(f3.x) + fabsf(f3.y);
                rw[(r * 4 + dl) * 33 + l] = (s0 + s1) + (s2 + s3);
            }
        }
        __syncwarp();

        // ---- transpose-reduce: lane pair per (row,d) entry ----
        const int e = l & 15;                    // e = row*4 + dl
        const int h = l >> 4;
        const float* rr = rw + e * 33 + h * 16;
        float s0 = 0.f, s1 = 0.f, s2 = 0.f, s3 = 0.f;
#pragma unroll
        for (int j = 0; j < 16; j += 4) {
            s0 += rr[j + 0]; s1 += rr[j + 1];
            s2 += rr[j + 2]; s3 += rr[j + 3];
        }
        float dist = (s0 + s1) + (s2 + s3);
        dist += __shfl_xor_sync(0xffffffffu, dist, 16);
        const float wv = -0.5f * dist;           // logits = -dist/SCALE, SCALE=2

        // ---- per-warp online softmax; rescale only when max improves ----
        float cm = wv;
        cm = fmaxf(cm, __shfl_xor_sync(0xffffffffu, cm, 1));
        cm = fmaxf(cm, __shfl_xor_sync(0xffffffffu, cm, 2));
        if (__any_sync(0xffffffffu, cm > m_own)) {
            const float mnew = fmaxf(m_own, cm);
            const float corr = __expf(m_own - mnew);
            m_own = mnew;
            lsum_own *= corr;
#pragma unroll
            for (int r = 0; r < 4; r++) {
                const float cr = __shfl_sync(0xffffffffu, corr, r * 4);
                const ull c2 = dup2(cr);
#pragma unroll
                for (int j = 0; j < 4; j++) acc[r][j] = mul2(acc[r][j], c2);
            }
        }
        const float pv = __expf(wv - m_own);
        float ps = pv + __shfl_xor_sync(0xffffffffu, pv, 1);
        ps += __shfl_xor_sync(0xffffffffu, ps, 2);
        lsum_own += ps;

        // ---- P @ V: packed FMA, p broadcast via shfl ----
#pragma unroll
        for (int dl = 0; dl < 4; dl++) {
            const int d = ds * 4 + dl;
            const ulonglong2 va = *(const ulonglong2*)(vc + d * SS + 4 * l);
            const ulonglong2 vb = *(const ulonglong2*)(vc + d * SS + 128 + 4 * l);
#pragma unroll
            for (int r = 0; r < 4; r++) {
                const float pj = __shfl_sync(0xffffffffu, pv, r * 4 + dl);
                const ull p2 = dup2(pj);
                acc[r][0] = fma2(p2, va.x, acc[r][0]);
                acc[r][1] = fma2(p2, va.y, acc[r][1]);
                acc[r][2] = fma2(p2, vb.x, acc[r][2]);
                acc[r][3] = fma2(p2, vb.y, acc[r][3]);
            }
        }

        // done reading stage st for this chunk: per-warp arrive
        if (l == 0) mbar_arrive(mb_empty + 8u * st);

        // producer: refill this stage with chunk ch+3 once all warps released it
        if (tid == 0 && ch + NSTAGE < NCHUNK) {
            mbar_wait(mb_empty + 8u * st, (unsigned)(rnd & 1));
            mbar_expect_tx(mb_full + 8u * st, 2 * CHUNK_BYTES);
            bulk_g2s(ks + st * STAGE_FLOATS,
                     kbase + (size_t)(ch + NSTAGE) * STAGE_FLOATS,
                     CHUNK_BYTES, mb_full + 8u * st);
            bulk_g2s(vs + st * STAGE_FLOATS,
                     vbase + (size_t)(ch + NSTAGE) * STAGE_FLOATS,
                     CHUNK_BYTES, mb_full + 8u * st);
        }

        if (++st == NSTAGE) { st = 0; rnd++; }
    }

    __syncthreads();   // all warps done with all stages; smem reusable

    // ================= epilogue: merge the 8 d-split segments =================
    float* accbuf = smem;                        // [8 rows][8 splits][256]
    float* stats  = smem + 8 * 8 * 256;          // [8 rows][8 splits][2]

#pragma unroll
    for (int r = 0; r < 4; r++) {
        const int row = g * 4 + r;
        float* dst = accbuf + (row * 8 + ds) * 256;
        *(ulonglong2*)(dst + 4 * l)       = make_ulonglong2(acc[r][0], acc[r][1]);
        *(ulonglong2*)(dst + 128 + 4 * l) = make_ulonglong2(acc[r][2], acc[r][3]);
    }
    if (l < 16 && (l & 3) == 0) {
        const int row = g * 4 + (l >> 2);
        stats[(row * 8 + ds) * 2 + 0] = m_own;
        stats[(row * 8 + ds) * 2 + 1] = lsum_own;
    }
    __syncthreads();

    {
        const int row  = w >> 1;
        const int half = w & 1;
        const int sb   = half * 128 + l * 4;

        float M = -1e30f;
#pragma unroll
        for (int i = 0; i < 8; i++) M = fmaxf(M, stats[(row * 8 + i) * 2]);

        float L = 0.f;
        ull o0 = 0ULL, o1 = 0ULL;
#pragma unroll
        for (int i = 0; i < 8; i++) {
            const float sc = __expf(stats[(row * 8 + i) * 2] - M);
            L += stats[(row * 8 + i) * 2 + 1] * sc;
            const ulonglong2 a = *(const ulonglong2*)(accbuf + (row * 8 + i) * 256 + sb);
            const ull s2 = dup2(sc);
            o0 = fma2(s2, a.x, o0);
            o1 = fma2(s2, a.y, o1);
        }
        const ull i2 = dup2(1.f / L);
        o0 = mul2(o0, i2);
        o1 = mul2(o1, i2);

        const int c = ct * 8 + row;
        *(ulonglong2*)(out + ((size_t)n * CC + c) * SS + sb) = make_ulonglong2(o0, o1);
    }
}

extern "C" void kernel_launch(void* const* d_in, const int* in_sizes, int n_in,
                              void* d_out, int out_size) {
    const float* q = (const float*)d_in[0];
    const float* k = (const float*)d_in[1];
    const float* v = (const float*)d_in[2];
    float* out = (float*)d_out;

    cudaFuncSetAttribute(laplace_attn_kernel,
                         cudaFuncAttributeMaxDynamicSharedMemorySize, SMEM_BYTES);

    laplace_attn_kernel<<<NB * (CC / 8), THREADS, SMEM_BYTES>>>(q, k, v, out);
}